// round 6
// baseline (speedup 1.0000x reference)
#include <cuda_runtime.h>
#include <math.h>

#define Bn 4
#define GLn 4
#define Nn 1024
#define CSn 32
#define CNn 16
#define NAn 16
#define Sn 512
#define Rn 128     // GL*CS
#define K1n 512    // GL*GF
#define IKn 128    // CS*GL
#define JUn 512    // CN*CS
#define GRID 296   // 148 SMs x 2 co-resident blocks

// -------- scratch (device globals; no allocations anywhere) --------
__device__ float g_u[Bn*Rn*Nn];          // primary caps pre-squash, [b][m=128][n=1024]
__device__ float g_msqp[Bn*GLn*8];       // squash-norm partials per (b,g,nblk)
__device__ float g_WgT[IKn*JUn];         // permuted Wg: [ik=128][ju=512]
__device__ float g_V[Bn*Nn*JUn];         // routing v
__device__ float g_apart[Bn*16*8*64];    // agreement partials [b][msplit][jub][i*2+jg]
__device__ float g_blog[Bn*CSn*CNn];     // routing logits
__device__ float g_gpart[Bn*64*JUn];     // column-sum partials of final v
__device__ float g_va[Bn*NAn*CSn];       // aspect routing output
__device__ unsigned g_barcnt[8];         // grid barrier counters (monotonic, epoch-inferred)

// ---------------- tf32 helpers ----------------
__device__ __forceinline__ unsigned f2tf(float f){
    unsigned r; asm("cvt.rna.tf32.f32 %0, %1;" : "=r"(r) : "f"(f)); return r;
}
__device__ __forceinline__ void mma_tf32(float* d, unsigned a0, unsigned a1,
                                         unsigned a2, unsigned a3,
                                         unsigned b0, unsigned b1){
    asm volatile(
        "mma.sync.aligned.m16n8k8.row.col.f32.tf32.tf32.f32 "
        "{%0,%1,%2,%3}, {%4,%5,%6,%7}, {%8,%9}, {%0,%1,%2,%3};"
        : "+f"(d[0]), "+f"(d[1]), "+f"(d[2]), "+f"(d[3])
        : "r"(a0), "r"(a1), "r"(a2), "r"(a3), "r"(b0), "r"(b1));
}

// ---------------- grid-wide barrier (epoch-inference; replay-safe) ----------------
__device__ __forceinline__ void gbar(int p){
    __threadfence();            // publish this thread's writes
    __syncthreads();            // all block threads published
    if (threadIdx.x == 0){
        unsigned old = atomicAdd(&g_barcnt[p], 1u);
        unsigned target = (old/GRID + 1u)*GRID;
        while (*((volatile unsigned*)&g_barcnt[p]) < target) __nanosleep(64);
        __threadfence();        // acquire side
    }
    __syncthreads();
}

// ---------------- phase: primary caps GEMM (tf32) + squash-norm partials ----------------
__device__ __forceinline__ void ph_primary(int u, const float* __restrict__ Wp,
                                           const float* __restrict__ bp,
                                           const float* __restrict__ X, float* sp){
    unsigned* shA = (unsigned*)sp;          // [32][20]
    unsigned* shB = (unsigned*)sp + 640;    // [16][136]
    float* red = sp + 2816;                 // [256]
    int b = u >> 5, mb = (u >> 3) & 3, nb = u & 7;
    int m0 = mb*32, n0 = nb*128;
    const float* Xb = X + (size_t)b*K1n*Nn;
    int tid = threadIdx.x;
    int w = tid >> 5, lane = tid & 31, gid = lane >> 2, t4 = lane & 3;
    int wm = w >> 2, wn = w & 3;
    __syncthreads();
    float d[4][4] = {};
    for (int k0 = 0; k0 < K1n; k0 += 16){
        #pragma unroll
        for (int e = tid; e < 512; e += 256){
            int m = e >> 4, k = e & 15;
            shA[m*20 + k] = f2tf(Wp[(m0+m)*K1n + k0 + k]);
        }
        #pragma unroll
        for (int e = tid; e < 2048; e += 256){
            int k = e >> 7, n = e & 127;
            shB[k*136 + n] = f2tf(Xb[(size_t)(k0+k)*Nn + n0 + n]);
        }
        __syncthreads();
        #pragma unroll
        for (int ks = 0; ks < 2; ks++){
            unsigned a0 = shA[(wm*16+gid  )*20 + ks*8+t4  ];
            unsigned a1 = shA[(wm*16+gid+8)*20 + ks*8+t4  ];
            unsigned a2 = shA[(wm*16+gid  )*20 + ks*8+t4+4];
            unsigned a3 = shA[(wm*16+gid+8)*20 + ks*8+t4+4];
            #pragma unroll
            for (int nt = 0; nt < 4; nt++){
                int n = wn*32 + nt*8 + gid;
                unsigned b0 = shB[(ks*8+t4  )*136 + n];
                unsigned b1 = shB[(ks*8+t4+4)*136 + n];
                mma_tf32(d[nt], a0, a1, a2, a3, b0, b1);
            }
        }
        __syncthreads();
    }
    int mA = m0 + wm*16 + gid, mB = mA + 8;
    float biasA = bp[mA], biasB = bp[mB];
    float ssq = 0.f;
    #pragma unroll
    for (int nt = 0; nt < 4; nt++){
        int n = n0 + wn*32 + nt*8 + t4*2;
        float v0 = d[nt][0] + biasA, v1 = d[nt][1] + biasA;
        float v2 = d[nt][2] + biasB, v3 = d[nt][3] + biasB;
        *(float2*)&g_u[(size_t)b*Rn*Nn + (size_t)mA*Nn + n] = make_float2(v0, v1);
        *(float2*)&g_u[(size_t)b*Rn*Nn + (size_t)mB*Nn + n] = make_float2(v2, v3);
        ssq += v0*v0 + v1*v1 + v2*v2 + v3*v3;
    }
    red[tid] = ssq; __syncthreads();
    for (int off = 128; off; off >>= 1){
        if (tid < off) red[tid] += red[tid+off];
        __syncthreads();
    }
    if (tid == 0)
        g_msqp[(b*GLn + mb)*8 + nb] = red[0];
}

// ---------------- phase: routing-s GEMM (tf32) + squash ----------------
__device__ __forceinline__ void ph_route(int u, int iter, float* sp){
    float* SM    = sp;                       // [16][520]
    float* c_shf = sp + 8320;                // [32][16]
    float* fb    = sp + 8832;                // [512]
    float* scp   = sp + 9344;                // [1]
    unsigned* shA  = (unsigned*)sp;          // [16][132] = 2112
    unsigned* bufB = (unsigned*)sp + 2112;   // [8][520]  = 4160 (ends 6272 < 8320)
    int b = u >> 6, mblk = u & 63;
    int m0 = mblk*16;
    int tid = threadIdx.x;
    int w = tid >> 5, lane = tid & 31, gid = lane >> 2, t4 = lane & 3;
    __syncthreads();
    if (tid == 0){
        int grp = m0 >> 8;
        float s = 0.f;
        #pragma unroll
        for (int t = 0; t < 8; t++) s += g_msqp[(b*GLn + grp)*8 + t];
        scp[0] = sqrtf(s)/(1.f + s);
    }
    if (iter >= 1){
        for (int e = tid; e < 512; e += 256){
            float s = (iter == 2) ? g_blog[b*512 + e] : 0.f;
            int i = e >> 4, j = e & 15;
            #pragma unroll
            for (int ms = 0; ms < 16; ms++)
                s += g_apart[((b*16 + ms)*8 + (j >> 1))*64 + i*2 + (j & 1)];
            fb[e] = s;
        }
    }
    __syncthreads();
    float sc = scp[0];
    if (iter == 1 && mblk == 0)
        for (int e = tid; e < 512; e += 256) g_blog[b*512 + e] = fb[e];
    if (iter >= 1 && tid < 32){
        int i = tid;
        float row[CNn], mx = -1e30f;
        #pragma unroll
        for (int j = 0; j < CNn; j++){ row[j] = fb[i*16 + j]; mx = fmaxf(mx, row[j]); }
        float sum = 0.f;
        #pragma unroll
        for (int j = 0; j < CNn; j++){ row[j] = expf(row[j]-mx); sum += row[j]; }
        float inv = 1.f/sum;
        #pragma unroll
        for (int j = 0; j < CNn; j++) c_shf[i*16 + j] = row[j]*inv;
    }
    {
        const float* U = g_u + (size_t)b*Nn*IKn + (size_t)m0*IKn;
        #pragma unroll
        for (int e = tid; e < 2048; e += 256){
            int m = e >> 7, k = e & 127;
            shA[m*132 + k] = f2tf(U[(size_t)m*IKn + k]*sc);
        }
    }
    __syncthreads();

    float d[8][4] = {};
    const bool unif = (iter == 0);
    for (int k0 = 0; k0 < IKn; k0 += 8){
        #pragma unroll
        for (int e = tid; e < 4096; e += 256){
            int kk = e >> 9, n = e & 511;
            float wv = g_WgT[(size_t)(k0+kk)*JUn + n];
            float val = unif ? wv*0.0625f : wv*c_shf[((k0+kk) & 31)*16 + (n >> 5)];
            bufB[kk*520 + n] = f2tf(val);
        }
        __syncthreads();
        unsigned a0 = shA[ gid   *132 + k0 + t4  ];
        unsigned a1 = shA[(gid+8)*132 + k0 + t4  ];
        unsigned a2 = shA[ gid   *132 + k0 + t4+4];
        unsigned a3 = shA[(gid+8)*132 + k0 + t4+4];
        #pragma unroll
        for (int nt = 0; nt < 8; nt++){
            int n = w*64 + nt*8 + gid;
            unsigned b0 = bufB[ t4   *520 + n];
            unsigned b1 = bufB[(t4+4)*520 + n];
            mma_tf32(d[nt], a0, a1, a2, a3, b0, b1);
        }
        __syncthreads();
    }
    #pragma unroll
    for (int nt = 0; nt < 8; nt++){
        int n = w*64 + nt*8 + t4*2;
        SM[ gid   *520 + n    ] = d[nt][0];
        SM[ gid   *520 + n + 1] = d[nt][1];
        SM[(gid+8)*520 + n    ] = d[nt][2];
        SM[(gid+8)*520 + n + 1] = d[nt][3];
    }
    __syncthreads();
    if (iter < 2){
        float* Vp = g_V + (size_t)b*Nn*JUn;
        for (int e = tid; e < 512; e += 256){
            int m = e >> 5, uu = e & 31;
            float msq = 0.f;
            #pragma unroll
            for (int j = 0; j < CNn; j++){
                float v = SM[m*520 + j*32 + uu];
                msq += v*v;
            }
            float fac = sqrtf(msq)/(1.f + msq);
            #pragma unroll
            for (int j = 0; j < CNn; j++)
                Vp[(size_t)(m0+m)*JUn + j*32 + uu] = SM[m*520 + j*32 + uu]*fac;
        }
    } else {
        for (int e = tid; e < 512; e += 256){
            int m = e >> 5, uu = e & 31;
            float msq = 0.f;
            #pragma unroll
            for (int j = 0; j < CNn; j++){
                float v = SM[m*520 + j*32 + uu];
                msq += v*v;
            }
            float fac = sqrtf(msq)/(1.f + msq);
            #pragma unroll
            for (int j = 0; j < CNn; j++)
                SM[m*520 + j*32 + uu] *= fac;
        }
        __syncthreads();
        for (int col = tid; col < 512; col += 256){
            float s = 0.f;
            #pragma unroll
            for (int m = 0; m < 16; m++) s += SM[m*520 + col];
            g_gpart[((size_t)b*64 + mblk)*JUn + col] = s;
        }
    }
}

// ---------------- phase: T GEMM (tf32) + fused agreement ----------------
__device__ __forceinline__ void ph_T(int u, float* sp){
    unsigned* shUT = (unsigned*)sp;          // [128][20] = 2560
    unsigned* shV  = (unsigned*)sp + 2560;   // [16][72]  = 1152
    float* shAg = sp + 3712;                 // [8][32]
    float* scp  = sp + 3968;                 // [1]
    int b = u >> 7, msb = (u >> 3) & 15, nblk = u & 7;
    int n0 = nblk*64, mbase = msb*64;
    int tid = threadIdx.x;
    int w = tid >> 5, lane = tid & 31, gid = lane >> 2, t4 = lane & 3;
    int wik = w >> 1, wju = w & 1;
    __syncthreads();
    if (tid == 0){
        int grp = mbase >> 8;
        float s = 0.f;
        #pragma unroll
        for (int t = 0; t < 8; t++) s += g_msqp[(b*GLn + grp)*8 + t];
        scp[0] = sqrtf(s)/(1.f + s);
    }
    __syncthreads();
    float sc = scp[0];
    const float* U = g_u + (size_t)b*Nn*IKn;
    const float* V = g_V + (size_t)b*Nn*JUn;
    float d[2][4][4] = {};
    for (int mc = 0; mc < 64; mc += 16){
        int mm0 = mbase + mc;
        #pragma unroll
        for (int e = tid; e < 2048; e += 256){
            int m = e >> 7, ik = e & 127;
            shUT[ik*20 + m] = f2tf(U[(size_t)(mm0+m)*IKn + ik]*sc);
        }
        #pragma unroll
        for (int e = tid; e < 1024; e += 256){
            int m = e >> 6, n = e & 63;
            shV[m*72 + n] = f2tf(V[(size_t)(mm0+m)*JUn + n0 + n]);
        }
        __syncthreads();
        #pragma unroll
        for (int ks = 0; ks < 2; ks++){
            unsigned bb[4][2];
            #pragma unroll
            for (int nt = 0; nt < 4; nt++){
                int n = wju*32 + nt*8 + gid;
                bb[nt][0] = shV[(ks*8+t4  )*72 + n];
                bb[nt][1] = shV[(ks*8+t4+4)*72 + n];
            }
            #pragma unroll
            for (int mt = 0; mt < 2; mt++){
                int r = wik*32 + mt*16;
                unsigned a0 = shUT[(r+gid  )*20 + ks*8+t4  ];
                unsigned a1 = shUT[(r+gid+8)*20 + ks*8+t4  ];
                unsigned a2 = shUT[(r+gid  )*20 + ks*8+t4+4];
                unsigned a3 = shUT[(r+gid+8)*20 + ks*8+t4+4];
                #pragma unroll
                for (int nt = 0; nt < 4; nt++)
                    mma_tf32(d[mt][nt], a0, a1, a2, a3, bb[nt][0], bb[nt][1]);
            }
        }
        __syncthreads();
    }
    float p[2][2] = {};
    #pragma unroll
    for (int mt = 0; mt < 2; mt++){
        int r0 = wik*32 + mt*16 + gid, r1 = r0 + 8;
        #pragma unroll
        for (int nt = 0; nt < 4; nt++){
            int col = n0 + wju*32 + nt*8 + t4*2;
            float2 w0 = *(const float2*)&g_WgT[(size_t)r0*JUn + col];
            float2 w1 = *(const float2*)&g_WgT[(size_t)r1*JUn + col];
            p[mt][0] += d[mt][nt][0]*w0.x + d[mt][nt][1]*w0.y;
            p[mt][1] += d[mt][nt][2]*w1.x + d[mt][nt][3]*w1.y;
        }
    }
    #pragma unroll
    for (int mt = 0; mt < 2; mt++)
        #pragma unroll
        for (int h = 0; h < 2; h++){
            p[mt][h] += __shfl_xor_sync(0xffffffffu, p[mt][h], 1);
            p[mt][h] += __shfl_xor_sync(0xffffffffu, p[mt][h], 2);
        }
    if (t4 == 0){
        shAg[w*32 + 0*16 + 0 + gid] = p[0][0];
        shAg[w*32 + 0*16 + 8 + gid] = p[0][1];
        shAg[w*32 + 1*16 + 0 + gid] = p[1][0];
        shAg[w*32 + 1*16 + 8 + gid] = p[1][1];
    }
    __syncthreads();
    if (tid < 64){
        int i = tid >> 1, jg = tid & 1;
        float s = 0.f;
        #pragma unroll
        for (int k = 0; k < 4; k++) s += shAg[(k*2 + jg)*32 + i];
        g_apart[((b*16 + msb)*8 + nblk)*64 + i*2 + jg] = s*(1.f/1024.f);
    }
}

// ---------------- phase: aspect (hidden cancels; M collapses to 1) ----------------
__device__ __forceinline__ void ph_aspect(int b, const float* __restrict__ Wa,
                                          const float* __restrict__ Ws, float* sp){
    float* g    = sp;            // [16][32]
    float* cond = sp + 512;      // [16][32]
    float* uh   = sp + 1024;     // [16][16][32]
    float* b2   = sp + 9216;     // [16][16]
    float* c2   = sp + 9472;     // [16][16]
    float* s2   = sp + 9728;     // [16][32]
    float* v2   = sp + 10240;    // [16][32]
    float* facu = sp + 10752;    // [32]
    float* score= sp + 10784;    // [16]
    int tid = threadIdx.x;
    __syncthreads();
    const float invN = 1.f/1024.f;
    for (int e = tid; e < JUn; e += 256){
        float t = 0.f;
        #pragma unroll
        for (int s = 0; s < 64; s++) t += g_gpart[((size_t)b*64 + s)*JUn + e];
        g[e] = t*invN;
    }
    __syncthreads();
    if (tid == 0){
        float gw[CNn], mx = -1e30f;
        for (int i = 0; i < CNn; i++){
            float s = 0.f;
            for (int uu = 0; uu < CSn; uu++) s += g[i*32+uu]*Wa[uu];
            gw[i] = s; mx = fmaxf(mx, s);
        }
        float sum = 0.f;
        for (int i = 0; i < CNn; i++){ gw[i] = expf(gw[i]-mx); sum += gw[i]; }
        float inv = 1.f/sum;
        for (int i = 0; i < CNn; i++) score[i] = gw[i]*inv;
    }
    __syncthreads();
    for (int e = tid; e < JUn; e += 256)
        cond[e] = g[e]*score[e>>5];
    { int i = tid >> 4, j = tid & 15; b2[i*16+j] = 0.f; }
    __syncthreads();
    for (int e = tid; e < CNn*NAn*CSn; e += 256){
        int i = e >> 9, j = (e >> 5) & 15, uu = e & 31;
        float s = 0.f;
        const float* wrow = Ws + ((size_t)((i*NAn+j)*CSn+uu))*CSn;
        #pragma unroll
        for (int k = 0; k < CSn; k++) s += wrow[k]*cond[i*32+k];
        uh[e] = s;
    }
    __syncthreads();
    for (int it = 0; it < 3; it++){
        if (tid < CNn){
            int i = tid;
            float mx = -1e30f;
            #pragma unroll
            for (int j = 0; j < NAn; j++) mx = fmaxf(mx, b2[i*16+j]);
            float sum = 0.f, r[NAn];
            #pragma unroll
            for (int j = 0; j < NAn; j++){ r[j] = expf(b2[i*16+j]-mx); sum += r[j]; }
            float inv = 1.f/sum;
            #pragma unroll
            for (int j = 0; j < NAn; j++) c2[i*16+j] = r[j]*inv;
        }
        __syncthreads();
        for (int e = tid; e < NAn*CSn; e += 256){
            int j = e >> 5, uu = e & 31;
            float s = 0.f;
            #pragma unroll
            for (int i = 0; i < CNn; i++) s += c2[i*16+j]*uh[(i*NAn+j)*CSn+uu];
            s2[e] = s;
        }
        __syncthreads();
        if (tid < CSn){
            int uu = tid; float ms = 0.f;
            #pragma unroll
            for (int j = 0; j < NAn; j++) ms += s2[j*32+uu]*s2[j*32+uu];
            facu[uu] = sqrtf(ms)/(1.f+ms);
        }
        __syncthreads();
        for (int e = tid; e < NAn*CSn; e += 256)
            v2[e] = s2[e]*facu[e & 31];
        __syncthreads();
        if (it < 2){
            {
                int i = tid >> 4, j = tid & 15;
                float a = 0.f;
                #pragma unroll
                for (int uu = 0; uu < CSn; uu++) a += uh[(i*NAn+j)*CSn+uu]*v2[j*32+uu];
                b2[i*16+j] += a;
            }
            __syncthreads();
        }
    }
    for (int e = tid; e < NAn*CSn; e += 256)
        g_va[b*NAn*CSn + e] = v2[e];
}

// ---------------- the single persistent kernel ----------------
__global__ __launch_bounds__(256, 2) void k_mega(const float* __restrict__ ge,
                                                 const float* __restrict__ Wp,
                                                 const float* __restrict__ bp,
                                                 const float* __restrict__ Wg,
                                                 const float* __restrict__ Wa,
                                                 const float* __restrict__ Ws,
                                                 float* __restrict__ out){
    __shared__ float sp[11264];   // 45KB pool, carved per phase
    int bid = blockIdx.x;
    int tid = threadIdx.x;

    // P0: permW (first 256 blocks, 1 elem each slot) + primary GEMM (128 units)
    {
        int e = bid*256 + tid;
        if (e < IKn*JUn){
            int ik = e >> 9, ju = e & 511;
            int k = ik >> 5, i = ik & 31, j = ju >> 5, uu = ju & 31;
            g_WgT[e] = Wg[((i*CNn + j)*CSn + uu)*GLn + k];
        }
    }
    for (int u = bid; u < 128; u += GRID) ph_primary(u, Wp, bp, ge, sp);
    gbar(0);

    for (int u = bid; u < 256; u += GRID) ph_route(u, 0, sp);
    gbar(1);
    for (int u = bid; u < 512; u += GRID) ph_T(u, sp);
    gbar(2);
    for (int u = bid; u < 256; u += GRID) ph_route(u, 1, sp);
    gbar(3);
    for (int u = bid; u < 512; u += GRID) ph_T(u, sp);
    gbar(4);
    for (int u = bid; u < 256; u += GRID) ph_route(u, 2, sp);
    gbar(5);

    if (bid < Bn) ph_aspect(bid, Wa, Ws, sp);
    gbar(6);

    // broadcast: out[b][s][e] = g_va[b][e], float4-vectorized
    const float4* va4 = (const float4*)g_va;
    float4* out4 = (float4*)out;
    for (int i4 = bid*256 + tid; i4 < Bn*Sn*128; i4 += GRID*256){
        int b = i4 >> 16;                 // 512 rows * 128 f4 per batch
        out4[i4] = va4[(b << 7) + (i4 & 127)];
    }
}

extern "C" void kernel_launch(void* const* d_in, const int* in_sizes, int n_in,
                              void* d_out, int out_size){
    (void)in_sizes; (void)n_in; (void)out_size;
    const float* ge = (const float*)d_in[0];
    // d_in[1] = hidden: cancels exactly in the softmax over capsules; never read.
    const float* Wp = (const float*)d_in[2];
    const float* bp = (const float*)d_in[3];
    const float* Wg = (const float*)d_in[4];
    const float* Wa = (const float*)d_in[5];
    const float* Ws = (const float*)d_in[6];
    float* out = (float*)d_out;

    k_mega<<<GRID, 256>>>(ge, Wp, bp, Wg, Wa, Ws, out);
}

// round 7
// speedup vs baseline: 1.3303x; 1.3303x over previous
#include <cuda_runtime.h>
#include <math.h>

#define Bn 4
#define GLn 4
#define Nn 1024
#define CSn 32
#define CNn 16
#define NAn 16
#define Sn 512
#define IKn 128
#define JUn 512

// -------- scratch (device globals; no allocations anywhere) --------
__device__ float    g_u[Bn*128*1024];     // primary caps pre-squash fp32 (flat [b][m][ik] view)
__device__ float    g_msqp[Bn*4*32];      // squash-norm partials per (b, gl, 32)
__device__ float    g_WgT[128*512];       // fp32 Wg permuted: [ik=k*32+i][col'=u*16+j]
__device__ unsigned g_Wpt[128*512];       // tf32 Wp
__device__ unsigned g_Xt[Bn*512*1024];    // tf32 graph_embed
__device__ unsigned g_Ut[Bn*1024*128];    // tf32 scaled U  [b][m][ik]
__device__ unsigned g_W1t[Bn*128*512];    // tf32 c-weighted Wg [b][ik][col']
__device__ unsigned g_V[Bn*1024*512];     // tf32 routing v [b][m][col']
__device__ float    g_apart[Bn*8*8*512];  // agreement partials [b][msb][nblk][i*16+j]
__device__ float    g_blog[Bn*512];       // routing logits
__device__ float    g_gpart[Bn*8*512];    // colsum partials of final v [b][mblk][col']
__device__ float    g_va[Bn*NAn*CSn];     // aspect output

// ---------------- helpers ----------------
__device__ __forceinline__ unsigned f2tf(float f){
    unsigned r; asm("cvt.rna.tf32.f32 %0, %1;" : "=r"(r) : "f"(f)); return r;
}
__device__ __forceinline__ void mma_tf32(float* d, unsigned a0, unsigned a1,
                                         unsigned a2, unsigned a3,
                                         unsigned b0, unsigned b1){
    asm volatile(
        "mma.sync.aligned.m16n8k8.row.col.f32.tf32.tf32.f32 "
        "{%0,%1,%2,%3}, {%4,%5,%6,%7}, {%8,%9}, {%0,%1,%2,%3};"
        : "+f"(d[0]), "+f"(d[1]), "+f"(d[2]), "+f"(d[3])
        : "r"(a0), "r"(a1), "r"(a2), "r"(a3), "r"(b0), "r"(b1));
}
__device__ __forceinline__ unsigned s2u(const void* p){
    return (unsigned)__cvta_generic_to_shared(p);
}
__device__ __forceinline__ void cpa16(unsigned d, const void* s){
    asm volatile("cp.async.cg.shared.global [%0], [%1], 16;" :: "r"(d), "l"(s));
}
__device__ __forceinline__ void cpa_commit(){ asm volatile("cp.async.commit_group;"); }
template<int N> __device__ __forceinline__ void cpa_wait(){
    asm volatile("cp.async.wait_group %0;" :: "n"(N));
}

// ---------------- permute Wg + convert Wp, X to tf32 ----------------
__global__ __launch_bounds__(256) void k_permW(const float* __restrict__ Wg,
                                               const float* __restrict__ Wp,
                                               const float* __restrict__ X){
    int bid = blockIdx.x, tid = threadIdx.x;
    if (bid < 256){
        int e = bid*256 + tid;
        int ik = e >> 9, col = e & 511;
        int u = col >> 4, j = col & 15, i = ik & 31, k = ik >> 5;
        g_WgT[e] = Wg[((i*16 + j)*32 + u)*4 + k];
        g_Wpt[e] = f2tf(Wp[e]);
    } else {
        int e4 = (bid - 256)*256 + tid;   // < 524288
        float4 x = ((const float4*)X)[e4];
        uint4 r; r.x=f2tf(x.x); r.y=f2tf(x.y); r.z=f2tf(x.z); r.w=f2tf(x.w);
        ((uint4*)g_Xt)[e4] = r;
    }
}

// ---------------- primary GEMM: 128m x 64n per block, k=512, double-buffered ----------------
__global__ __launch_bounds__(256) void k_primary(const float* __restrict__ bp){
    __shared__ __align__(16) unsigned sA[2][2560];  // [128m][20]
    __shared__ __align__(16) unsigned sB[2][1152];  // [16k][72]
    __shared__ float red[8];
    int n0 = blockIdx.x*64, b = blockIdx.y;
    int tid = threadIdx.x, w = tid>>5, lane = tid&31, gid = lane>>2, t4 = lane&3;
    int wm = w>>1, wn = w&1;
    const unsigned* Ag = g_Wpt;
    const unsigned* Bg = g_Xt + (size_t)b*524288;

    #define PRIM_STAGE(ch, bf) { \
        { int f = tid;      int row=f>>2, q=f&3;  cpa16(s2u(&sA[bf][row*20+q*4]), Ag + row*512 + (ch)*16 + q*4); } \
        { int f = tid+256;  int row=f>>2, q=f&3;  cpa16(s2u(&sA[bf][row*20+q*4]), Ag + row*512 + (ch)*16 + q*4); } \
        { int f = tid;      int row=f>>4, q=f&15; cpa16(s2u(&sB[bf][row*72+q*4]), Bg + (size_t)((ch)*16+row)*1024 + n0 + q*4); } \
        cpa_commit(); }

    float d[2][4][4] = {};
    PRIM_STAGE(0, 0);
    for (int ch = 0; ch < 32; ch++){
        int buf = ch & 1;
        if (ch < 31){ PRIM_STAGE(ch+1, buf^1); cpa_wait<1>(); } else cpa_wait<0>();
        __syncthreads();
        #pragma unroll
        for (int ks = 0; ks < 2; ks++){
            unsigned a[2][4];
            #pragma unroll
            for (int mt = 0; mt < 2; mt++){
                int rb = (wm*32 + mt*16 + gid)*20 + ks*8 + t4;
                a[mt][0]=sA[buf][rb]; a[mt][1]=sA[buf][rb+320]; a[mt][2]=sA[buf][rb+4]; a[mt][3]=sA[buf][rb+324];
            }
            #pragma unroll
            for (int nt = 0; nt < 4; nt++){
                int cb = wn*32 + nt*8 + gid;
                unsigned b0 = sB[buf][(ks*8+t4)*72 + cb];
                unsigned b1 = sB[buf][(ks*8+t4+4)*72 + cb];
                mma_tf32(d[0][nt], a[0][0],a[0][1],a[0][2],a[0][3], b0, b1);
                mma_tf32(d[1][nt], a[1][0],a[1][1],a[1][2],a[1][3], b0, b1);
            }
        }
        __syncthreads();
    }
    float ssq = 0.f;
    #pragma unroll
    for (int mt = 0; mt < 2; mt++){
        int mA = wm*32 + mt*16 + gid, mB = mA + 8;
        float biasA = bp[mA], biasB = bp[mB];
        #pragma unroll
        for (int nt = 0; nt < 4; nt++){
            int col = n0 + wn*32 + nt*8 + t4*2;
            float v0 = d[mt][nt][0]+biasA, v1 = d[mt][nt][1]+biasA;
            float v2 = d[mt][nt][2]+biasB, v3 = d[mt][nt][3]+biasB;
            *(float2*)&g_u[(size_t)b*131072 + (size_t)mA*1024 + col] = make_float2(v0,v1);
            *(float2*)&g_u[(size_t)b*131072 + (size_t)mB*1024 + col] = make_float2(v2,v3);
            ssq += v0*v0+v1*v1+v2*v2+v3*v3;
        }
    }
    #pragma unroll
    for (int o = 16; o; o >>= 1) ssq += __shfl_xor_sync(0xffffffffu, ssq, o);
    if (lane == 0) red[w] = ssq;
    __syncthreads();
    if (tid < 8)
        g_msqp[(b*4 + (tid>>1))*32 + blockIdx.x*2 + (tid&1)] = red[tid];
}

// ---------------- prep: fold logits, softmax c, build W1t (+Ut at iter 0) ----------------
__global__ __launch_bounds__(256) void k_prep(int iter){
    __shared__ float c_sm[32][16];
    __shared__ float fb[512];
    __shared__ float scf[4];
    int bx = blockIdx.x, b = blockIdx.y, tid = threadIdx.x;
    if (iter >= 1){
        #pragma unroll
        for (int r = 0; r < 2; r++){
            int e = r*256 + tid;
            float s = (iter == 2) ? g_blog[b*512 + e] : 0.f;
            const float* ap = g_apart + (size_t)b*32768 + e;
            #pragma unroll
            for (int t = 0; t < 64; t++) s += ap[t*512];
            fb[e] = s;
        }
    }
    if (iter == 0 && tid < 4){
        float s = 0.f;
        #pragma unroll
        for (int t = 0; t < 32; t++) s += g_msqp[(b*4 + tid)*32 + t];
        scf[tid] = sqrtf(s)/(1.f + s);
    }
    __syncthreads();
    if (iter == 1 && bx == 0)
        for (int e = tid; e < 512; e += 256) g_blog[b*512 + e] = fb[e];
    if (iter >= 1 && tid < 32){
        int i = tid;
        float row[CNn], mx = -1e30f;
        #pragma unroll
        for (int j = 0; j < CNn; j++){ row[j] = fb[i*16 + j]; mx = fmaxf(mx, row[j]); }
        float sum = 0.f;
        #pragma unroll
        for (int j = 0; j < CNn; j++){ row[j] = expf(row[j]-mx); sum += row[j]; }
        float inv = 1.f/sum;
        #pragma unroll
        for (int j = 0; j < CNn; j++) c_sm[i][j] = row[j]*inv;
    }
    __syncthreads();
    // W1t: 1024 f4 per block
    const float4* Wt4 = (const float4*)g_WgT;
    uint4* W1 = (uint4*)(g_W1t + (size_t)b*65536);
    #pragma unroll
    for (int r = 0; r < 4; r++){
        int e4 = bx*1024 + r*256 + tid;
        float4 wv = Wt4[e4];
        int e = e4*4;
        int i = (e >> 9) & 31, jb = e & 15;
        float c0,c1,c2,c3;
        if (iter == 0){ c0=c1=c2=c3=0.0625f; }
        else { c0=c_sm[i][jb]; c1=c_sm[i][jb+1]; c2=c_sm[i][jb+2]; c3=c_sm[i][jb+3]; }
        uint4 o; o.x=f2tf(wv.x*c0); o.y=f2tf(wv.y*c1); o.z=f2tf(wv.z*c2); o.w=f2tf(wv.w*c3);
        W1[e4] = o;
    }
    if (iter == 0){
        const float4* U4 = (const float4*)(g_u + (size_t)b*131072);
        uint4* Ut4 = (uint4*)(g_Ut + (size_t)b*131072);
        #pragma unroll
        for (int r = 0; r < 8; r++){
            int e4 = bx*2048 + r*256 + tid;
            float sc = scf[e4 >> 13];          // m = e4>>5, gl = m>>8
            float4 uv = U4[e4];
            uint4 o; o.x=f2tf(uv.x*sc); o.y=f2tf(uv.y*sc); o.z=f2tf(uv.z*sc); o.w=f2tf(uv.w*sc);
            Ut4[e4] = o;
        }
    }
}

// ---------------- route GEMM: 128m x 128col' per block, k=128, fused squash ----------------
__global__ __launch_bounds__(256) void k_route(int iter){
    __shared__ __align__(16) unsigned sA[2][2560];   // [128m][20]
    __shared__ __align__(16) unsigned sB[2][2176];   // [16k][136]
    __shared__ float cs_sm[2][128];
    int c0 = blockIdx.x*128, m0 = blockIdx.y*128, b = blockIdx.z;
    int tid = threadIdx.x, w = tid>>5, lane = tid&31, gid = lane>>2, t4 = lane&3;
    int wm = w>>2, wn = w&3;
    const unsigned* Ag = g_Ut + (size_t)b*131072 + (size_t)m0*128;
    const unsigned* Bg = g_W1t + (size_t)b*65536;

    #define ROUTE_STAGE(ch, bf) { \
        { int f = tid;      int row=f>>2, q=f&3;  cpa16(s2u(&sA[bf][row*20+q*4]), Ag + row*128 + (ch)*16 + q*4); } \
        { int f = tid+256;  int row=f>>2, q=f&3;  cpa16(s2u(&sA[bf][row*20+q*4]), Ag + row*128 + (ch)*16 + q*4); } \
        { int f = tid;      int row=f>>5, q=f&31; cpa16(s2u(&sB[bf][row*136+q*4]), Bg + (size_t)((ch)*16+row)*512 + c0 + q*4); } \
        { int f = tid+256;  int row=f>>5, q=f&31; cpa16(s2u(&sB[bf][row*136+q*4]), Bg + (size_t)((ch)*16+row)*512 + c0 + q*4); } \
        cpa_commit(); }

    float d[4][4][4] = {};
    ROUTE_STAGE(0, 0);
    for (int ch = 0; ch < 8; ch++){
        int buf = ch & 1;
        if (ch < 7){ ROUTE_STAGE(ch+1, buf^1); cpa_wait<1>(); } else cpa_wait<0>();
        __syncthreads();
        #pragma unroll
        for (int ks = 0; ks < 2; ks++){
            unsigned a[4][4];
            #pragma unroll
            for (int mt = 0; mt < 4; mt++){
                int rb = (wm*64 + mt*16 + gid)*20 + ks*8 + t4;
                a[mt][0]=sA[buf][rb]; a[mt][1]=sA[buf][rb+160]; a[mt][2]=sA[buf][rb+4]; a[mt][3]=sA[buf][rb+164];
            }
            #pragma unroll
            for (int nt = 0; nt < 4; nt++){
                int cb = wn*32 + nt*8 + gid;
                unsigned b0 = sB[buf][(ks*8+t4)*136 + cb];
                unsigned b1 = sB[buf][(ks*8+t4+4)*136 + cb];
                #pragma unroll
                for (int mt = 0; mt < 4; mt++)
                    mma_tf32(d[mt][nt], a[mt][0],a[mt][1],a[mt][2],a[mt][3], b0, b1);
            }
        }
        __syncthreads();
    }
    // squash: j spans quad(t4) x {nt-parity} x {c}; u groups: nt<2 vs nt>=2
    #pragma unroll
    for (int mt = 0; mt < 4; mt++){
        #pragma unroll
        for (int off = 0; off < 2; off++){
            float p0 = d[mt][0][off*2]*d[mt][0][off*2] + d[mt][0][off*2+1]*d[mt][0][off*2+1]
                     + d[mt][1][off*2]*d[mt][1][off*2] + d[mt][1][off*2+1]*d[mt][1][off*2+1];
            float p1 = d[mt][2][off*2]*d[mt][2][off*2] + d[mt][2][off*2+1]*d[mt][2][off*2+1]
                     + d[mt][3][off*2]*d[mt][3][off*2] + d[mt][3][off*2+1]*d[mt][3][off*2+1];
            p0 += __shfl_xor_sync(0xffffffffu, p0, 1); p0 += __shfl_xor_sync(0xffffffffu, p0, 2);
            p1 += __shfl_xor_sync(0xffffffffu, p1, 1); p1 += __shfl_xor_sync(0xffffffffu, p1, 2);
            float f0 = sqrtf(p0)/(1.f + p0), f1 = sqrtf(p1)/(1.f + p1);
            d[mt][0][off*2] *= f0; d[mt][0][off*2+1] *= f0;
            d[mt][1][off*2] *= f0; d[mt][1][off*2+1] *= f0;
            d[mt][2][off*2] *= f1; d[mt][2][off*2+1] *= f1;
            d[mt][3][off*2] *= f1; d[mt][3][off*2+1] *= f1;
        }
    }
    if (iter < 2){
        unsigned* Vg = g_V + (size_t)b*524288;
        #pragma unroll
        for (int mt = 0; mt < 4; mt++)
            #pragma unroll
            for (int off = 0; off < 2; off++){
                int m = m0 + wm*64 + mt*16 + gid + off*8;
                #pragma unroll
                for (int nt = 0; nt < 4; nt++){
                    int col = c0 + wn*32 + nt*8 + t4*2;
                    uint2 pv; pv.x = f2tf(d[mt][nt][off*2]); pv.y = f2tf(d[mt][nt][off*2+1]);
                    *(uint2*)&Vg[(size_t)m*512 + col] = pv;
                }
            }
    } else {
        #pragma unroll
        for (int nt = 0; nt < 4; nt++)
            #pragma unroll
            for (int c = 0; c < 2; c++){
                float s = 0.f;
                #pragma unroll
                for (int mt = 0; mt < 4; mt++) s += d[mt][nt][c] + d[mt][nt][2+c];
                s += __shfl_xor_sync(0xffffffffu, s, 4);
                s += __shfl_xor_sync(0xffffffffu, s, 8);
                s += __shfl_xor_sync(0xffffffffu, s, 16);
                if (gid == 0) cs_sm[wm][wn*32 + nt*8 + t4*2 + c] = s;
            }
        __syncthreads();
        if (tid < 128)
            g_gpart[((size_t)b*8 + blockIdx.y)*512 + c0 + tid] = cs_sm[0][tid] + cs_sm[1][tid];
    }
}

// ---------------- T GEMM (128ik x 64col' x 128m) + fused agreement ----------------
__global__ __launch_bounds__(256) void k_T(){
    __shared__ __align__(16) unsigned sU[2][2176];  // [16m][136]
    __shared__ __align__(16) unsigned sV[2][1152];  // [16m][72]
    __shared__ float sag[4096];
    int n0 = blockIdx.x*64, mbase = blockIdx.y*128, b = blockIdx.z;
    int tid = threadIdx.x, w = tid>>5, lane = tid&31, gid = lane>>2, t4 = lane&3;
    int wik = w>>1, wju = w&1;
    const unsigned* Ug = g_Ut + (size_t)b*131072 + (size_t)mbase*128;
    const unsigned* Vg = g_V + (size_t)b*524288 + (size_t)mbase*512;

    #define T_STAGE(ch, bf) { \
        { int f=tid;      int row=f>>5, q=f&31; cpa16(s2u(&sU[bf][row*136+q*4]), Ug + (size_t)((ch)*16+row)*128 + q*4); } \
        { int f=tid+256;  int row=f>>5, q=f&31; cpa16(s2u(&sU[bf][row*136+q*4]), Ug + (size_t)((ch)*16+row)*128 + q*4); } \
        { int f=tid;      int row=f>>4, q=f&15; cpa16(s2u(&sV[bf][row*72+q*4]), Vg + (size_t)((ch)*16+row)*512 + n0 + q*4); } \
        cpa_commit(); }

    float d[2][4][4] = {};
    T_STAGE(0, 0);
    for (int ch = 0; ch < 8; ch++){
        int buf = ch & 1;
        if (ch < 7){ T_STAGE(ch+1, buf^1); cpa_wait<1>(); } else cpa_wait<0>();
        __syncthreads();
        #pragma unroll
        for (int ks = 0; ks < 2; ks++){
            unsigned a[2][4];
            #pragma unroll
            for (int mt = 0; mt < 2; mt++){
                int ikb = wik*32 + mt*16 + gid;
                a[mt][0] = sU[buf][(ks*8+t4)*136 + ikb];
                a[mt][1] = sU[buf][(ks*8+t4)*136 + ikb + 8];
                a[mt][2] = sU[buf][(ks*8+t4+4)*136 + ikb];
                a[mt][3] = sU[buf][(ks*8+t4+4)*136 + ikb + 8];
            }
            #pragma unroll
            for (int nt = 0; nt < 4; nt++){
                int cb = wju*32 + nt*8 + gid;
                unsigned b0 = sV[buf][(ks*8+t4)*72 + cb];
                unsigned b1 = sV[buf][(ks*8+t4+4)*72 + cb];
                mma_tf32(d[0][nt], a[0][0],a[0][1],a[0][2],a[0][3], b0, b1);
                mma_tf32(d[1][nt], a[1][0],a[1][1],a[1][2],a[1][3], b0, b1);
            }
        }
        __syncthreads();
    }
    // agreement: dot T tile with WgT (fp32), accumulate per (i,j)
    float p[4][4] = {};
    #pragma unroll
    for (int mt = 0; mt < 2; mt++)
        #pragma unroll
        for (int off = 0; off < 2; off++){
            int r = wik*32 + mt*16 + off*8 + gid;
            #pragma unroll
            for (int nt = 0; nt < 4; nt++){
                int col = n0 + wju*32 + nt*8 + t4*2;
                float2 wv = *(const float2*)&g_WgT[(size_t)r*512 + col];
                int pi = mt*2 + off, js = (nt & 1)*2;
                p[pi][js]   += d[mt][nt][off*2]   * wv.x;
                p[pi][js+1] += d[mt][nt][off*2+1] * wv.y;
            }
        }
    #pragma unroll
    for (int pi = 0; pi < 4; pi++)
        #pragma unroll
        for (int js = 0; js < 4; js++)
            sag[(w*32 + lane)*16 + pi*4 + js] = p[pi][js];
    __syncthreads();
    #pragma unroll
    for (int it = 0; it < 2; it++){
        int idx = it*256 + tid;
        int i = idx >> 4, j = idx & 15;
        int lgid = i & 7, pi = ((i>>4)<<1) | ((i>>3)&1);
        int lt4 = (j & 7) >> 1, js = ((j>>3)<<1) | (j&1);
        int ln = lgid*4 + lt4;
        float s = 0.f;
        #pragma unroll
        for (int ww = 0; ww < 8; ww++) s += sag[(ww*32 + ln)*16 + pi*4 + js];
        g_apart[(((size_t)b*8 + blockIdx.y)*8 + blockIdx.x)*512 + idx] = s*(1.f/1024.f);
    }
}

// ---------------- aspect stage (hidden cancels; M collapses to 1) ----------------
__global__ __launch_bounds__(256) void k_aspect(const float* __restrict__ Wa,
                                                const float* __restrict__ Ws){
    __shared__ float g[CNn][CSn];
    __shared__ float cond[CNn][CSn];
    __shared__ float uh[CNn][NAn][CSn];
    __shared__ float b2[CNn][NAn];
    __shared__ float c2[CNn][NAn];
    __shared__ float s2[NAn][CSn];
    __shared__ float v2[NAn][CSn];
    __shared__ float facu[CSn];
    __shared__ float score[CNn];
    int b = blockIdx.x, tid = threadIdx.x;
    const float invN = 1.f/1024.f;
    for (int e = tid; e < JUn; e += 256){
        int j = e >> 5, u = e & 31;
        float t = 0.f;
        #pragma unroll
        for (int mb = 0; mb < 8; mb++) t += g_gpart[((size_t)b*8 + mb)*512 + u*16 + j];
        g[j][u] = t*invN;
    }
    __syncthreads();
    if (tid == 0){
        float gw[CNn], mx = -1e30f;
        for (int i = 0; i < CNn; i++){
            float s = 0.f;
            for (int u = 0; u < CSn; u++) s += g[i][u]*Wa[u];
            gw[i] = s; mx = fmaxf(mx, s);
        }
        float sum = 0.f;
        for (int i = 0; i < CNn; i++){ gw[i] = expf(gw[i]-mx); sum += gw[i]; }
        float inv = 1.f/sum;
        for (int i = 0; i < CNn; i++) score[i] = gw[i]*inv;
    }
    __syncthreads();
    for (int e = tid; e < JUn; e += 256)
        cond[e>>5][e&31] = g[e>>5][e&31]*score[e>>5];
    { int i = tid >> 4, j = tid & 15; b2[i][j] = 0.f; }
    __syncthreads();
    for (int e = tid; e < CNn*NAn*CSn; e += 256){
        int i = e >> 9, j = (e >> 5) & 15, u = e & 31;
        float s = 0.f;
        const float* wrow = Ws + ((size_t)((i*NAn+j)*CSn+u))*CSn;
        #pragma unroll
        for (int k = 0; k < CSn; k++) s += wrow[k]*cond[i][k];
        uh[i][j][u] = s;
    }
    __syncthreads();
    for (int it = 0; it < 3; it++){
        if (tid < CNn){
            int i = tid;
            float mx = -1e30f;
            #pragma unroll
            for (int j = 0; j < NAn; j++) mx = fmaxf(mx, b2[i][j]);
            float sum = 0.f, r[NAn];
            #pragma unroll
            for (int j = 0; j < NAn; j++){ r[j] = expf(b2[i][j]-mx); sum += r[j]; }
            float inv = 1.f/sum;
            #pragma unroll
            for (int j = 0; j < NAn; j++) c2[i][j] = r[j]*inv;
        }
        __syncthreads();
        for (int e = tid; e < NAn*CSn; e += 256){
            int j = e >> 5, u = e & 31;
            float s = 0.f;
            #pragma unroll
            for (int i = 0; i < CNn; i++) s += c2[i][j]*uh[i][j][u];
            s2[j][u] = s;
        }
        __syncthreads();
        if (tid < CSn){
            int u = tid; float ms = 0.f;
            #pragma unroll
            for (int j = 0; j < NAn; j++) ms += s2[j][u]*s2[j][u];
            facu[u] = sqrtf(ms)/(1.f+ms);
        }
        __syncthreads();
        for (int e = tid; e < NAn*CSn; e += 256){
            int j = e >> 5, u = e & 31;
            v2[j][u] = s2[j][u]*facu[u];
        }
        __syncthreads();
        if (it < 2){
            {
                int i = tid >> 4, j = tid & 15;
                float a = 0.f;
                #pragma unroll
                for (int u = 0; u < CSn; u++) a += uh[i][j][u]*v2[j][u];
                b2[i][j] += a;
            }
            __syncthreads();
        }
    }
    for (int e = tid; e < NAn*CSn; e += 256)
        g_va[b*NAn*CSn + e] = v2[e>>5][e&31];
}

// ---------------- broadcast final v to all S rows ----------------
__global__ __launch_bounds__(256) void k_broadcast(float* __restrict__ out){
    int i4 = blockIdx.x*256 + threadIdx.x;   // < 262144
    int b = i4 >> 16;
    ((float4*)out)[i4] = ((const float4*)g_va)[(b<<7) + (i4 & 127)];
}

extern "C" void kernel_launch(void* const* d_in, const int* in_sizes, int n_in,
                              void* d_out, int out_size){
    (void)in_sizes; (void)n_in; (void)out_size;
    const float* ge = (const float*)d_in[0];
    // d_in[1] = hidden: cancels exactly in the softmax over capsules; never read.
    const float* Wp = (const float*)d_in[2];
    const float* bp = (const float*)d_in[3];
    const float* Wg = (const float*)d_in[4];
    const float* Wa = (const float*)d_in[5];
    const float* Ws = (const float*)d_in[6];
    float* out = (float*)d_out;

    k_permW<<<2304, 256>>>(Wg, Wp, ge);
    k_primary<<<dim3(16, 4), 256>>>(bp);
    for (int t = 0; t < 3; t++){
        k_prep<<<dim3(16, 4), 256>>>(t);
        k_route<<<dim3(4, 8, 4), 256>>>(t);
        if (t < 2)
            k_T<<<dim3(8, 8, 4), 256>>>();
    }
    k_aspect<<<Bn, 256>>>(Wa, Ws);
    k_broadcast<<<1024, 256>>>(out);
}

// round 8
// speedup vs baseline: 1.3703x; 1.0301x over previous
#include <cuda_runtime.h>
#include <math.h>

#define Bn 4
#define CNn 16
#define NAn 16
#define CSn 32
#define JUn 512
#define GRID 256

// -------- scratch (device globals; no allocations anywhere) --------
__device__ float    g_msqp[Bn*4*32];      // squash-norm partials (b, gl, 32)
__device__ float    g_WgT[128*512];       // fp32 Wg permuted: [ik=k*32+i][col'=u*16+j]
__device__ unsigned g_Wpt[128*512];       // tf32 Wp
__device__ unsigned g_Xt[Bn*512*1024];    // tf32 graph_embed
__device__ unsigned g_Ut[Bn*1024*128];    // tf32 UNSCALED U (flat reinterpret view)
__device__ unsigned g_V[Bn*1024*512];     // tf32 routing v [b][m][col']
__device__ float    g_apart[Bn*8*8*512];  // agreement partials [b][msb][nblk][i*16+j]
__device__ float    g_blog[Bn*512];       // routing logits
__device__ float    g_gpart[Bn*8*512];    // colsum partials of final v [b][mblk][col']
__device__ float    g_va[Bn*NAn*CSn];     // aspect output
__device__ unsigned g_barcnt[8];          // grid barrier counters (monotonic)

// ---------------- helpers ----------------
__device__ __forceinline__ unsigned f2tf(float f){
    unsigned r; asm("cvt.rna.tf32.f32 %0, %1;" : "=r"(r) : "f"(f)); return r;
}
__device__ __forceinline__ void mma_tf32(float* d, unsigned a0, unsigned a1,
                                         unsigned a2, unsigned a3,
                                         unsigned b0, unsigned b1){
    asm volatile(
        "mma.sync.aligned.m16n8k8.row.col.f32.tf32.tf32.f32 "
        "{%0,%1,%2,%3}, {%4,%5,%6,%7}, {%8,%9}, {%0,%1,%2,%3};"
        : "+f"(d[0]), "+f"(d[1]), "+f"(d[2]), "+f"(d[3])
        : "r"(a0), "r"(a1), "r"(a2), "r"(a3), "r"(b0), "r"(b1));
}
__device__ __forceinline__ unsigned s2u(const void* p){
    return (unsigned)__cvta_generic_to_shared(p);
}
__device__ __forceinline__ void cpa16(unsigned d, const void* s){
    asm volatile("cp.async.cg.shared.global [%0], [%1], 16;" :: "r"(d), "l"(s));
}
__device__ __forceinline__ void cpa_commit(){ asm volatile("cp.async.commit_group;"); }
template<int N> __device__ __forceinline__ void cpa_wait(){
    asm volatile("cp.async.wait_group %0;" :: "n"(N));
}
__device__ __forceinline__ void gbar(int p){
    __threadfence();
    __syncthreads();
    if (threadIdx.x == 0){
        unsigned old = atomicAdd(&g_barcnt[p], 1u);
        unsigned target = (old/GRID + 1u)*GRID;
        while (*((volatile unsigned*)&g_barcnt[p]) < target) __nanosleep(64);
        __threadfence();
    }
    __syncthreads();
}

// ---------------- phase: primary GEMM 128m x 64n, k=512 ----------------
__device__ __forceinline__ void ph_primary(int u, const float* __restrict__ bp, float* sp){
    unsigned* sA = (unsigned*)sp;          // [2][2560]
    unsigned* sB = (unsigned*)sp + 5120;   // [2][1152]
    float* red = sp + 7424;                // [8]
    int b = u >> 4, n0 = (u & 15)*64;
    int tid = threadIdx.x, w = tid>>5, lane = tid&31, gid = lane>>2, t4 = lane&3;
    int wm = w>>1, wn = w&1;
    const unsigned* Ag = g_Wpt;
    const unsigned* Bg = g_Xt + (size_t)b*524288;
    float d[2][4][4] = {};

#define PRIM_STAGE(ch, bf) { \
    { int f=tid;     int row=f>>2,q=f&3;  cpa16(s2u(&sA[(bf)*2560+row*20+q*4]), Ag + row*512 + (ch)*16 + q*4); } \
    { int f=tid+256; int row=f>>2,q=f&3;  cpa16(s2u(&sA[(bf)*2560+row*20+q*4]), Ag + row*512 + (ch)*16 + q*4); } \
    { int f=tid;     int row=f>>4,q=f&15; cpa16(s2u(&sB[(bf)*1152+row*72+q*4]), Bg + (size_t)((ch)*16+row)*1024 + n0 + q*4); } \
    cpa_commit(); }

    PRIM_STAGE(0,0);
    for (int ch = 0; ch < 32; ch++){
        int buf = ch & 1;
        if (ch < 31){ PRIM_STAGE(ch+1, buf^1); cpa_wait<1>(); } else cpa_wait<0>();
        __syncthreads();
        #pragma unroll
        for (int ks = 0; ks < 2; ks++){
            unsigned a[2][4];
            #pragma unroll
            for (int mt = 0; mt < 2; mt++){
                int rb = buf*2560 + (wm*32 + mt*16 + gid)*20 + ks*8 + t4;
                a[mt][0]=sA[rb]; a[mt][1]=sA[rb+160]; a[mt][2]=sA[rb+4]; a[mt][3]=sA[rb+164];
            }
            #pragma unroll
            for (int nt = 0; nt < 4; nt++){
                int cb = buf*1152 + (ks*8+t4)*72 + wn*32 + nt*8 + gid;
                unsigned b0 = sB[cb], b1 = sB[cb + 288];
                mma_tf32(d[0][nt], a[0][0],a[0][1],a[0][2],a[0][3], b0, b1);
                mma_tf32(d[1][nt], a[1][0],a[1][1],a[1][2],a[1][3], b0, b1);
            }
        }
        __syncthreads();
    }
    float ssq = 0.f;
    unsigned* Ub = g_Ut + (size_t)b*131072;
    #pragma unroll
    for (int mt = 0; mt < 2; mt++){
        int mA = wm*32 + mt*16 + gid, mB = mA + 8;
        float biasA = bp[mA], biasB = bp[mB];
        #pragma unroll
        for (int nt = 0; nt < 4; nt++){
            int col = n0 + wn*32 + nt*8 + t4*2;
            float v0 = d[mt][nt][0]+biasA, v1 = d[mt][nt][1]+biasA;
            float v2 = d[mt][nt][2]+biasB, v3 = d[mt][nt][3]+biasB;
            uint2 pa; pa.x = f2tf(v0); pa.y = f2tf(v1);
            uint2 pb; pb.x = f2tf(v2); pb.y = f2tf(v3);
            *(uint2*)&Ub[(size_t)mA*1024 + col] = pa;
            *(uint2*)&Ub[(size_t)mB*1024 + col] = pb;
            ssq += v0*v0+v1*v1+v2*v2+v3*v3;
        }
    }
    #pragma unroll
    for (int o = 16; o; o >>= 1) ssq += __shfl_xor_sync(0xffffffffu, ssq, o);
    if (lane == 0) red[w] = ssq;
    __syncthreads();
    if (tid < 8)
        g_msqp[(b*4 + (tid>>1))*32 + (u&15)*2 + (tid&1)] = red[tid];
}

// ---------------- phase: route GEMM 128m x 128col', k=128, fused prep+squash ----------------
__device__ __forceinline__ void ph_route(int u, int t, float* sp){
    unsigned* sA = (unsigned*)sp;            // [2][2560]
    unsigned* sB = (unsigned*)sp + 5120;     // [2][2176]
    float* c_smf = sp + 9472;                // [512] (reused as cs_sm later)
    float* fb    = sp + 9984;                // [512]
    float* scp   = sp + 10496;               // [1]
    int b = u >> 5, mblk = (u >> 2) & 7, cblk = u & 3;
    int m0 = mblk*128, c0 = cblk*128;
    int tid = threadIdx.x, w = tid>>5, lane = tid&31, gid = lane>>2, t4 = lane&3;
    int wm = w>>2, wn = w&3;

    // preamble: sc, logit fold, softmax (or uniform c)
    if (tid == 0){
        int grp = mblk >> 1;
        float s = 0.f;
        #pragma unroll
        for (int p = 0; p < 32; p++) s += g_msqp[(b*4+grp)*32 + p];
        scp[0] = sqrtf(s)/(1.f+s);
    }
    if (t >= 1){
        #pragma unroll
        for (int r = 0; r < 2; r++){
            int e = r*256 + tid;
            float s = (t == 2) ? g_blog[b*512 + e] : 0.f;
            const float* ap = g_apart + (size_t)b*32768 + e;
            #pragma unroll
            for (int p = 0; p < 64; p++) s += ap[p*512];
            fb[e] = s;
        }
    } else {
        c_smf[tid] = 0.0625f; c_smf[tid+256] = 0.0625f;
    }
    __syncthreads();
    if (t == 1 && mblk == 0 && cblk == 0)
        for (int e = tid; e < 512; e += 256) g_blog[b*512 + e] = fb[e];
    if (t >= 1 && tid < 32){
        int i = tid;
        float row[CNn], mx = -1e30f;
        #pragma unroll
        for (int j = 0; j < CNn; j++){ row[j] = fb[i*16 + j]; mx = fmaxf(mx, row[j]); }
        float sum = 0.f;
        #pragma unroll
        for (int j = 0; j < CNn; j++){ row[j] = expf(row[j]-mx); sum += row[j]; }
        float inv = 1.f/sum;
        #pragma unroll
        for (int j = 0; j < CNn; j++) c_smf[i*16 + j] = row[j]*inv;
    }
    __syncthreads();
    float sc = scp[0];

    const unsigned* Ag = g_Ut + (size_t)b*131072 + (size_t)m0*128;
    int brow = tid >> 4;              // 0..15 (k row within chunk)
    int bcol4 = (tid & 15)*2;         // f4 index within 32
    const float4* c4p0 = (const float4*)&c_smf[0];  // indexed by (i*4 + j4)

#define RT_STAGE_A(ch, bf) { \
    { int f=tid;     int row=f>>2,q=f&3; cpa16(s2u(&sA[(bf)*2560+row*20+q*4]), Ag + row*128 + (ch)*16 + q*4); } \
    { int f=tid+256; int row=f>>2,q=f&3; cpa16(s2u(&sA[(bf)*2560+row*20+q*4]), Ag + row*128 + (ch)*16 + q*4); } \
    cpa_commit(); }

    // B register prefetch for chunk 0
    float4 curB0, curB1;
    {
        const float4* src = (const float4*)(g_WgT + (size_t)brow*512 + c0) + bcol4;
        curB0 = src[0]; curB1 = src[1];
    }
    RT_STAGE_A(0, 0);
    float d[4][4][4] = {};
    for (int ch = 0; ch < 8; ch++){
        int buf = ch & 1;
        if (ch < 7) RT_STAGE_A(ch+1, buf^1);
        // weight + convert + store B chunk ch
        {
            int i = ((ch & 1)*16 + brow);
            float4 cv0 = c4p0[i*4 + (bcol4 & 3)];
            float4 cv1 = c4p0[i*4 + ((bcol4+1) & 3)];
            uint4 o0, o1;
            o0.x=f2tf(curB0.x*cv0.x); o0.y=f2tf(curB0.y*cv0.y);
            o0.z=f2tf(curB0.z*cv0.z); o0.w=f2tf(curB0.w*cv0.w);
            o1.x=f2tf(curB1.x*cv1.x); o1.y=f2tf(curB1.y*cv1.y);
            o1.z=f2tf(curB1.z*cv1.z); o1.w=f2tf(curB1.w*cv1.w);
            uint4* dst = (uint4*)&sB[buf*2176 + brow*136 + bcol4*4];
            dst[0] = o0; dst[1] = o1;
        }
        if (ch < 7){
            const float4* src = (const float4*)(g_WgT + (size_t)((ch+1)*16+brow)*512 + c0) + bcol4;
            curB0 = src[0]; curB1 = src[1];
        }
        if (ch < 7) cpa_wait<1>(); else cpa_wait<0>();
        __syncthreads();
        #pragma unroll
        for (int ks = 0; ks < 2; ks++){
            unsigned a[4][4];
            #pragma unroll
            for (int mt = 0; mt < 4; mt++){
                int rb = buf*2560 + (wm*64 + mt*16 + gid)*20 + ks*8 + t4;
                a[mt][0]=sA[rb]; a[mt][1]=sA[rb+160]; a[mt][2]=sA[rb+4]; a[mt][3]=sA[rb+164];
            }
            #pragma unroll
            for (int nt = 0; nt < 4; nt++){
                int cb = buf*2176 + (ks*8+t4)*136 + wn*32 + nt*8 + gid;
                unsigned b0 = sB[cb], b1 = sB[cb + 544];
                #pragma unroll
                for (int mt = 0; mt < 4; mt++)
                    mma_tf32(d[mt][nt], a[mt][0],a[mt][1],a[mt][2],a[mt][3], b0, b1);
            }
        }
        __syncthreads();
    }

    // squash over j (sc applied here; Ut is unscaled)
    #pragma unroll
    for (int mt = 0; mt < 4; mt++){
        #pragma unroll
        for (int off = 0; off < 2; off++){
            float p0 = d[mt][0][off*2]*d[mt][0][off*2] + d[mt][0][off*2+1]*d[mt][0][off*2+1]
                     + d[mt][1][off*2]*d[mt][1][off*2] + d[mt][1][off*2+1]*d[mt][1][off*2+1];
            float p1 = d[mt][2][off*2]*d[mt][2][off*2] + d[mt][2][off*2+1]*d[mt][2][off*2+1]
                     + d[mt][3][off*2]*d[mt][3][off*2] + d[mt][3][off*2+1]*d[mt][3][off*2+1];
            p0 += __shfl_xor_sync(0xffffffffu, p0, 1); p0 += __shfl_xor_sync(0xffffffffu, p0, 2);
            p1 += __shfl_xor_sync(0xffffffffu, p1, 1); p1 += __shfl_xor_sync(0xffffffffu, p1, 2);
            float q0 = sc*sc*p0, q1 = sc*sc*p1;
            float f0 = sc*sqrtf(q0)/(1.f + q0), f1 = sc*sqrtf(q1)/(1.f + q1);
            d[mt][0][off*2] *= f0; d[mt][0][off*2+1] *= f0;
            d[mt][1][off*2] *= f0; d[mt][1][off*2+1] *= f0;
            d[mt][2][off*2] *= f1; d[mt][2][off*2+1] *= f1;
            d[mt][3][off*2] *= f1; d[mt][3][off*2+1] *= f1;
        }
    }
    if (t < 2){
        unsigned* Vg = g_V + (size_t)b*524288;
        #pragma unroll
        for (int mt = 0; mt < 4; mt++)
            #pragma unroll
            for (int off = 0; off < 2; off++){
                int m = m0 + wm*64 + mt*16 + gid + off*8;
                #pragma unroll
                for (int nt = 0; nt < 4; nt++){
                    int col = c0 + wn*32 + nt*8 + t4*2;
                    uint2 pv; pv.x = f2tf(d[mt][nt][off*2]); pv.y = f2tf(d[mt][nt][off*2+1]);
                    *(uint2*)&Vg[(size_t)m*512 + col] = pv;
                }
            }
    } else {
        float* cs_sm = sp + 9472;   // [2][128]
        #pragma unroll
        for (int nt = 0; nt < 4; nt++)
            #pragma unroll
            for (int c = 0; c < 2; c++){
                float s = 0.f;
                #pragma unroll
                for (int mt = 0; mt < 4; mt++) s += d[mt][nt][c] + d[mt][nt][2+c];
                s += __shfl_xor_sync(0xffffffffu, s, 4);
                s += __shfl_xor_sync(0xffffffffu, s, 8);
                s += __shfl_xor_sync(0xffffffffu, s, 16);
                if (gid == 0) cs_sm[wm*128 + wn*32 + nt*8 + t4*2 + c] = s;
            }
        __syncthreads();
        if (tid < 128)
            g_gpart[((size_t)b*8 + mblk)*512 + c0 + tid] = cs_sm[tid] + cs_sm[128 + tid];
    }
}

// ---------------- phase: T GEMM (128ik x 64col' x 128m) + fused agreement ----------------
__device__ __forceinline__ void ph_T(int u, float* sp){
    unsigned* sU = (unsigned*)sp;            // [2][2176]
    unsigned* sV = (unsigned*)sp + 4352;     // [2][1152]
    float* sag = sp + 6656;                  // [4096]
    float* scp = sp + 10752;                 // [1]
    int b = u >> 6, msb = (u >> 3) & 7, nblk = u & 7;
    int n0 = nblk*64, mbase = msb*128;
    int tid = threadIdx.x, w = tid>>5, lane = tid&31, gid = lane>>2, t4 = lane&3;
    int wik = w>>1, wju = w&1;
    if (tid == 0){
        int grp = msb >> 1;
        float s = 0.f;
        #pragma unroll
        for (int p = 0; p < 32; p++) s += g_msqp[(b*4+grp)*32 + p];
        scp[0] = sqrtf(s)/(1.f+s);
    }
    __syncthreads();
    float sc = scp[0];
    const unsigned* Ug = g_Ut + (size_t)b*131072 + (size_t)mbase*128;
    const unsigned* Vg = g_V + (size_t)b*524288 + (size_t)mbase*512;

#define T_STAGE(ch, bf) { \
    { int f=tid;     int row=f>>5,q=f&31; cpa16(s2u(&sU[(bf)*2176+row*136+q*4]), Ug + (size_t)((ch)*16+row)*128 + q*4); } \
    { int f=tid+256; int row=f>>5,q=f&31; cpa16(s2u(&sU[(bf)*2176+row*136+q*4]), Ug + (size_t)((ch)*16+row)*128 + q*4); } \
    { int f=tid;     int row=f>>4,q=f&15; cpa16(s2u(&sV[(bf)*1152+row*72+q*4]), Vg + (size_t)((ch)*16+row)*512 + n0 + q*4); } \
    cpa_commit(); }

    float d[2][4][4] = {};
    T_STAGE(0, 0);
    for (int ch = 0; ch < 8; ch++){
        int buf = ch & 1;
        if (ch < 7){ T_STAGE(ch+1, buf^1); cpa_wait<1>(); } else cpa_wait<0>();
        __syncthreads();
        #pragma unroll
        for (int ks = 0; ks < 2; ks++){
            unsigned a[2][4];
            #pragma unroll
            for (int mt = 0; mt < 2; mt++){
                int ikb = wik*32 + mt*16 + gid;
                a[mt][0] = sU[buf*2176 + (ks*8+t4)*136 + ikb];
                a[mt][1] = sU[buf*2176 + (ks*8+t4)*136 + ikb + 8];
                a[mt][2] = sU[buf*2176 + (ks*8+t4+4)*136 + ikb];
                a[mt][3] = sU[buf*2176 + (ks*8+t4+4)*136 + ikb + 8];
            }
            #pragma unroll
            for (int nt = 0; nt < 4; nt++){
                int cb = wju*32 + nt*8 + gid;
                unsigned b0 = sV[buf*1152 + (ks*8+t4)*72 + cb];
                unsigned b1 = sV[buf*1152 + (ks*8+t4+4)*72 + cb];
                mma_tf32(d[0][nt], a[0][0],a[0][1],a[0][2],a[0][3], b0, b1);
                mma_tf32(d[1][nt], a[1][0],a[1][1],a[1][2],a[1][3], b0, b1);
            }
        }
        __syncthreads();
    }
    float p[4][4] = {};
    #pragma unroll
    for (int mt = 0; mt < 2; mt++)
        #pragma unroll
        for (int off = 0; off < 2; off++){
            int r = wik*32 + mt*16 + off*8 + gid;
            #pragma unroll
            for (int nt = 0; nt < 4; nt++){
                int col = n0 + wju*32 + nt*8 + t4*2;
                float2 wv = *(const float2*)&g_WgT[(size_t)r*512 + col];
                int pi = mt*2 + off, js = (nt & 1)*2;
                p[pi][js]   += d[mt][nt][off*2]   * wv.x;
                p[pi][js+1] += d[mt][nt][off*2+1] * wv.y;
            }
        }
    #pragma unroll
    for (int pi = 0; pi < 4; pi++)
        #pragma unroll
        for (int js = 0; js < 4; js++)
            sag[(w*32 + lane)*16 + pi*4 + js] = p[pi][js];
    __syncthreads();
    float wsc = sc*(1.f/1024.f);
    #pragma unroll
    for (int it = 0; it < 2; it++){
        int idx = it*256 + tid;
        int i = idx >> 4, j = idx & 15;
        int lgid = i & 7, pi = ((i>>4)<<1) | ((i>>3)&1);
        int lt4 = (j & 7) >> 1, js = ((j>>3)<<1) | (j&1);
        int ln = lgid*4 + lt4;
        float s = 0.f;
        #pragma unroll
        for (int ww = 0; ww < 8; ww++) s += sag[(ww*32 + ln)*16 + pi*4 + js];
        g_apart[(((size_t)b*8 + msb)*8 + nblk)*512 + idx] = s*wsc;
    }
}

// ---------------- phase: aspect (hidden cancels; M collapses to 1) ----------------
__device__ __forceinline__ void ph_aspect(int b, const float* __restrict__ Wa,
                                          const float* __restrict__ Ws, float* sp){
    float* g    = sp;            // [512]
    float* cond = sp + 512;
    float* uh   = sp + 1024;     // [8192]
    float* b2   = sp + 9216;
    float* c2   = sp + 9472;
    float* s2   = sp + 9728;
    float* v2   = sp + 10240;
    float* facu = sp + 10752;
    float* score= sp + 10784;
    int tid = threadIdx.x;
    const float invN = 1.f/1024.f;
    for (int e = tid; e < JUn; e += 256){
        int j = e >> 5, uu = e & 31;
        float t = 0.f;
        #pragma unroll
        for (int mb = 0; mb < 8; mb++) t += g_gpart[((size_t)b*8 + mb)*512 + uu*16 + j];
        g[j*32 + uu] = t*invN;
    }
    __syncthreads();
    if (tid == 0){
        float gw[CNn], mx = -1e30f;
        for (int i = 0; i < CNn; i++){
            float s = 0.f;
            for (int uu = 0; uu < CSn; uu++) s += g[i*32+uu]*Wa[uu];
            gw[i] = s; mx = fmaxf(mx, s);
        }
        float sum = 0.f;
        for (int i = 0; i < CNn; i++){ gw[i] = expf(gw[i]-mx); sum += gw[i]; }
        float inv = 1.f/sum;
        for (int i = 0; i < CNn; i++) score[i] = gw[i]*inv;
    }
    __syncthreads();
    for (int e = tid; e < JUn; e += 256)
        cond[e] = g[e]*score[e>>5];
    { int i = tid >> 4, j = tid & 15; b2[i*16+j] = 0.f; }
    __syncthreads();
    for (int e = tid; e < CNn*NAn*CSn; e += 256){
        int i = e >> 9, j = (e >> 5) & 15, uu = e & 31;
        float s = 0.f;
        const float* wrow = Ws + ((size_t)((i*NAn+j)*CSn+uu))*CSn;
        #pragma unroll
        for (int k = 0; k < CSn; k++) s += wrow[k]*cond[i*32+k];
        uh[e] = s;
    }
    __syncthreads();
    for (int it = 0; it < 3; it++){
        if (tid < CNn){
            int i = tid;
            float mx = -1e30f;
            #pragma unroll
            for (int j = 0; j < NAn; j++) mx = fmaxf(mx, b2[i*16+j]);
            float sum = 0.f, r[NAn];
            #pragma unroll
            for (int j = 0; j < NAn; j++){ r[j] = expf(b2[i*16+j]-mx); sum += r[j]; }
            float inv = 1.f/sum;
            #pragma unroll
            for (int j = 0; j < NAn; j++) c2[i*16+j] = r[j]*inv;
        }
        __syncthreads();
        for (int e = tid; e < NAn*CSn; e += 256){
            int j = e >> 5, uu = e & 31;
            float s = 0.f;
            #pragma unroll
            for (int i = 0; i < CNn; i++) s += c2[i*16+j]*uh[(i*NAn+j)*CSn+uu];
            s2[e] = s;
        }
        __syncthreads();
        if (tid < CSn){
            int uu = tid; float ms = 0.f;
            #pragma unroll
            for (int j = 0; j < NAn; j++) ms += s2[j*32+uu]*s2[j*32+uu];
            facu[uu] = sqrtf(ms)/(1.f+ms);
        }
        __syncthreads();
        for (int e = tid; e < NAn*CSn; e += 256)
            v2[e] = s2[e]*facu[e & 31];
        __syncthreads();
        if (it < 2){
            {
                int i = tid >> 4, j = tid & 15;
                float a = 0.f;
                #pragma unroll
                for (int uu = 0; uu < CSn; uu++) a += uh[(i*NAn+j)*CSn+uu]*v2[j*32+uu];
                b2[i*16+j] += a;
            }
            __syncthreads();
        }
    }
    for (int e = tid; e < NAn*CSn; e += 256)
        g_va[b*NAn*CSn + e] = v2[e];
}

// ---------------- the single persistent kernel ----------------
__global__ __launch_bounds__(256, 2) void k_mega(const float* __restrict__ ge,
                                                 const float* __restrict__ Wp,
                                                 const float* __restrict__ bp,
                                                 const float* __restrict__ Wg,
                                                 const float* __restrict__ Wa,
                                                 const float* __restrict__ Ws,
                                                 float* __restrict__ out){
    __shared__ __align__(16) float sp[11264];   // 44KB pool
    int bid = blockIdx.x;
    int tid = threadIdx.x;

    // P0: convert — WgT permute (fp32), Wpt tf32, Xt tf32
    #pragma unroll
    for (int r = 0; r < 2; r++){
        int e = bid*512 + r*256 + tid;
        int ik = e >> 9, col = e & 511;
        int uu = col >> 4, j = col & 15, i = ik & 31, k = ik >> 5;
        g_WgT[e] = Wg[((i*16 + j)*32 + uu)*4 + k];
    }
    { int e = bid*256 + tid; g_Wpt[e] = f2tf(Wp[e]); }
    #pragma unroll
    for (int r = 0; r < 8; r++){
        int e4 = bid*2048 + r*256 + tid;
        float4 x = ((const float4*)ge)[e4];
        uint4 o; o.x=f2tf(x.x); o.y=f2tf(x.y); o.z=f2tf(x.z); o.w=f2tf(x.w);
        ((uint4*)g_Xt)[e4] = o;
    }
    gbar(0);

    if (bid < 64) ph_primary(bid, bp, sp);
    gbar(1);

    if (bid < 128) ph_route(bid, 0, sp);
    gbar(2);
    ph_T(bid, sp);
    gbar(3);
    if (bid < 128) ph_route(bid, 1, sp);
    gbar(4);
    ph_T(bid, sp);
    gbar(5);
    if (bid < 128) ph_route(bid, 2, sp);
    gbar(6);

    if (bid < Bn) ph_aspect(bid, Wa, Ws, sp);
    gbar(7);

    // broadcast
    const float4* va4 = (const float4*)g_va;
    float4* out4 = (float4*)out;
    #pragma unroll
    for (int r = 0; r < 4; r++){
        int i4 = bid*1024 + r*256 + tid;
        int b = i4 >> 16;
        out4[i4] = va4[(b << 7) + (i4 & 127)];
    }
}

extern "C" void kernel_launch(void* const* d_in, const int* in_sizes, int n_in,
                              void* d_out, int out_size){
    (void)in_sizes; (void)n_in; (void)out_size;
    const float* ge = (const float*)d_in[0];
    // d_in[1] = hidden: cancels exactly in the softmax over capsules; never read.
    const float* Wp = (const float*)d_in[2];
    const float* bp = (const float*)d_in[3];
    const float* Wg = (const float*)d_in[4];
    const float* Wa = (const float*)d_in[5];
    const float* Ws = (const float*)d_in[6];
    float* out = (float*)d_out;

    k_mega<<<GRID, 256>>>(ge, Wp, bp, Wg, Wa, Ws, out);
}